// round 11
// baseline (speedup 1.0000x reference)
#include <cuda_runtime.h>

// TreePositionalEncodings — sm_100a, R10 resubmit (infra failure last round;
// kernel never ran): R3 strip design, STRIP=64.
//
// out[b, s, j]:
//   s == 0 or s > 1364  -> 0 ;  j >= 1020 -> 0
//   else                -> positions[0, s-1, j/51] * w[j]
// w[j] = tanh(p[j%51])^((j/51)/4) * sqrt((1-tanh^2)*1024/2)
//
// Roofline record (R1-R9): batch-scatter STG, contiguous-strip STG, TMA bulk
// store, STG+TMA hybrid, and L2::evict_last residency all converge on
// 42.6-44.2us kernel / ~45us total — the DRAM write-stream ceiling for a
// 256MB full-buffer overwrite (~4.9TB/s to DRAM, compute <10%). evict_last
// cut DRAM bytes but its L2-hit store path is ~2x slower: net loss.
// R10: STRIP 32->64 halves per-block prologue (tanhf+sync) and block count;
// store stream unchanged. Expected neutral to -1us.

#define D_MODEL   1024
#define MAX_LEN   2048
#define N_NODES   1364
#define BATCH     32
#define N_FEAT    51
#define N_DW      20
#define STRIP     64
#define STRIPS_PER_B (MAX_LEN / STRIP)   // 32
#define STRIP_SHIFT  5                   // log2(STRIPS_PER_B)

__global__ void __launch_bounds__(256) tree_pos_enc_strip_kernel(
    const float* __restrict__ p,           // [64], first 51 used
    const float* __restrict__ positions,   // [BS, N_NODES, N_DW]; b=0 slice used
    float* __restrict__ out)               // [BS, MAX_LEN, D_MODEL]
{
    __shared__ float s_tp[N_FEAT];
    __shared__ float s_norm[N_FEAT];
    __shared__ float s_pos[STRIP][N_DW];

    const int bx  = blockIdx.x;            // 0..1023
    const int b   = bx >> STRIP_SHIFT;     // batch 0..31
    const int s0  = (bx & (STRIPS_PER_B - 1)) * STRIP;  // first row of strip
    const int tid = threadIdx.x;           // 0..255, each owns 4 features

    // Weight params (51 tanhf, hidden under the store stream).
    if (tid < N_FEAT) {
        float tp = tanhf(p[tid]);
        s_tp[tid]   = tp;
        s_norm[tid] = sqrtf((1.0f - tp * tp) * (0.5f * (float)D_MODEL));
    }
    // Position rows for this strip; inactive rows (s==0 or s>N_NODES) -> 0,
    // so the store loop stays uniform and emits zeros for them.
    #pragma unroll
    for (int k = 0; k < (STRIP * N_DW + 255) / 256; k++) {
        int idx = tid + k * 256;
        if (idx < STRIP * N_DW) {
            int r = idx / N_DW, c = idx % N_DW;
            int s = s0 + r;
            float v = 0.0f;
            if (s >= 1 && s <= N_NODES)
                v = positions[(size_t)(s - 1) * N_DW + c];
            s_pos[r][c] = v;
        }
    }
    __syncthreads();

    // Per-thread loop-invariant weights + dw indices (4 features each).
    const int j = tid * 4;
    float w[4];
    int   dwv[4];
    #pragma unroll
    for (int e = 0; e < 4; e++) {
        int jj = j + e;
        int f  = jj % N_FEAT;              // const divisor -> magic mul
        int dw = jj / N_FEAT;              // 20 only for jj >= 1020 (zero pad)
        dwv[e] = (dw < N_DW) ? dw : 0;
        float ww = 0.0f;
        if (dw < N_DW) {
            float tp = s_tp[f];
            ww = s_norm[f];
            #pragma unroll 1
            for (int l = 0, lev = dw >> 2; l < lev; l++) ww *= tp;
        }
        w[e] = ww;
    }

    // Stream 64 consecutive 4KB rows: fully sequential 256KB per block.
    float4* o = reinterpret_cast<float4*>(out)
              + (size_t)b * (MAX_LEN * (D_MODEL / 4))
              + (size_t)s0 * (D_MODEL / 4) + tid;
    #pragma unroll 8
    for (int r = 0; r < STRIP; r++) {
        float4 v;
        v.x = w[0] * s_pos[r][dwv[0]];
        v.y = w[1] * s_pos[r][dwv[1]];
        v.z = w[2] * s_pos[r][dwv[2]];
        v.w = w[3] * s_pos[r][dwv[3]];
        __stcs(o + (size_t)r * (D_MODEL / 4), v);
    }
}

extern "C" void kernel_launch(void* const* d_in, const int* in_sizes, int n_in,
                              void* d_out, int out_size) {
    const float* p         = (const float*)d_in[0];   // [64]
    const float* positions = (const float*)d_in[1];   // [32, 1364, 20]
    float* out             = (float*)d_out;           // [32, 2048, 1024]

    tree_pos_enc_strip_kernel<<<BATCH * STRIPS_PER_B, 256>>>(p, positions, out);
}

// round 12
// speedup vs baseline: 1.0758x; 1.0758x over previous
#include <cuda_runtime.h>

// TreePositionalEncodings — sm_100a, FINAL (R3/R9 champion, STRIP=32).
//
// out[b, s, j]:
//   s == 0 or s > 1364  -> 0 ;  j >= 1020 -> 0
//   else                -> positions[0, s-1, j/51] * w[j]
// w[j] = tanh(p[j%51])^((j/51)/4) * sqrt((1-tanh^2)*1024/2)
//
// Session record (R1-R11): batch-scatter STG, contiguous-strip STG (32 & 64
// rows), TMA bulk store, STG+TMA hybrid, and L2::evict_last residency all
// measured. Every normal-path variant converges at ~42.6-44.4us kernel —
// the DRAM write-stream ceiling for a 256MB full-buffer overwrite
// (~4.9TB/s to DRAM, compute <10%, issue <25%). evict_last cut DRAM bytes
// but its L2-hit store path is ~2x slower (net +17us); STRIP=64 lost
// occupancy/wave balance (+3us). STRIP=32 strip is the verified optimum:
// 45.2us total.
//
// Design: block = one contiguous 128KB strip (batch b x 32 rows, 2048
// blocks). Weights (51 tanhf) rebuilt per-CTA under the store stream;
// per-thread loop-invariant w[4]; 32 sequential STG.128 rows, evict-first.

#define D_MODEL   1024
#define MAX_LEN   2048
#define N_NODES   1364
#define BATCH     32
#define N_FEAT    51
#define N_DW      20
#define STRIP     32
#define STRIPS_PER_B (MAX_LEN / STRIP)   // 64

__global__ void __launch_bounds__(256) tree_pos_enc_strip_kernel(
    const float* __restrict__ p,           // [64], first 51 used
    const float* __restrict__ positions,   // [BS, N_NODES, N_DW]; b=0 slice used
    float* __restrict__ out)               // [BS, MAX_LEN, D_MODEL]
{
    __shared__ float s_tp[N_FEAT];
    __shared__ float s_norm[N_FEAT];
    __shared__ float s_pos[STRIP][N_DW];

    const int bx  = blockIdx.x;            // 0..2047
    const int b   = bx >> 6;               // batch 0..31
    const int s0  = (bx & (STRIPS_PER_B - 1)) * STRIP;  // first row of strip
    const int tid = threadIdx.x;           // 0..255, each owns 4 features

    // Weight params (51 tanhf, hidden under the store stream).
    if (tid < N_FEAT) {
        float tp = tanhf(p[tid]);
        s_tp[tid]   = tp;
        s_norm[tid] = sqrtf((1.0f - tp * tp) * (0.5f * (float)D_MODEL));
    }
    // Position rows for this strip; inactive rows (s==0 or s>N_NODES) -> 0,
    // so the store loop stays uniform and emits zeros for them.
    #pragma unroll
    for (int k = 0; k < (STRIP * N_DW + 255) / 256; k++) {
        int idx = tid + k * 256;
        if (idx < STRIP * N_DW) {
            int r = idx / N_DW, c = idx % N_DW;
            int s = s0 + r;
            float v = 0.0f;
            if (s >= 1 && s <= N_NODES)
                v = positions[(size_t)(s - 1) * N_DW + c];
            s_pos[r][c] = v;
        }
    }
    __syncthreads();

    // Per-thread loop-invariant weights + dw indices (4 features each).
    const int j = tid * 4;
    float w[4];
    int   dwv[4];
    #pragma unroll
    for (int e = 0; e < 4; e++) {
        int jj = j + e;
        int f  = jj % N_FEAT;              // const divisor -> magic mul
        int dw = jj / N_FEAT;              // 20 only for jj >= 1020 (zero pad)
        dwv[e] = (dw < N_DW) ? dw : 0;
        float ww = 0.0f;
        if (dw < N_DW) {
            float tp = s_tp[f];
            ww = s_norm[f];
            #pragma unroll 1
            for (int l = 0, lev = dw >> 2; l < lev; l++) ww *= tp;
        }
        w[e] = ww;
    }

    // Stream 32 consecutive 4KB rows: fully sequential 128KB per block.
    float4* o = reinterpret_cast<float4*>(out)
              + (size_t)b * (MAX_LEN * (D_MODEL / 4))
              + (size_t)s0 * (D_MODEL / 4) + tid;
    #pragma unroll 8
    for (int r = 0; r < STRIP; r++) {
        float4 v;
        v.x = w[0] * s_pos[r][dwv[0]];
        v.y = w[1] * s_pos[r][dwv[1]];
        v.z = w[2] * s_pos[r][dwv[2]];
        v.w = w[3] * s_pos[r][dwv[3]];
        __stcs(o + (size_t)r * (D_MODEL / 4), v);
    }
}

extern "C" void kernel_launch(void* const* d_in, const int* in_sizes, int n_in,
                              void* d_out, int out_size) {
    const float* p         = (const float*)d_in[0];   // [64]
    const float* positions = (const float*)d_in[1];   // [32, 1364, 20]
    float* out             = (float*)d_out;           // [32, 2048, 1024]

    tree_pos_enc_strip_kernel<<<BATCH * STRIPS_PER_B, 256>>>(p, positions, out);
}